// round 16
// baseline (speedup 1.0000x reference)
#include <cuda_runtime.h>
#include <cuda_bf16.h>
#include <math.h>

#define NN 50000
#define NE 800000
#define PRE_BLOCKS 3125   // 16 nodes each
#define HIST_BLOCKS 3125  // 256 edges each

// ---------------- device scratch ----------------
__device__ float g_xl1[NN * 128];
__device__ float g_xr1[NN * 128];
__device__ float g_h1 [NN * 128];
__device__ float g_xl2[NN * 64];
__device__ float g_xr2[NN * 64];
__device__ int   g_cnt[NN];          // zeroed by agg2 of previous run (init: static zero)
__device__ int   g_rowptr[NN + 1];
__device__ int   g_blocksum[64];
__device__ int   g_scan_done;
__device__ int   g_src[NE];
__device__ float g_ea [NE];

__device__ __forceinline__ float ex2(float x) {
    float r;
    asm("ex2.approx.f32 %0, %1;" : "=f"(r) : "f"(x));
    return r;
}

// ---------------- launch 1: fused layer-1 projections + histogram ----------------
__global__ __launch_bounds__(256) void k_preHist(const float* __restrict__ x,
                                                 const float* __restrict__ Wl,
                                                 const float* __restrict__ Wr,
                                                 const int* __restrict__ ei) {
    if (blockIdx.x < PRE_BLOCKS) {
        __shared__ float swl[10 * 128];
        __shared__ float swr[10 * 128];
        int tid = threadIdx.x;
        int c = tid & 127;
        int h = tid >> 7;
        for (int k = tid; k < 10 * 128; k += 256) { swl[k] = Wl[k]; swr[k] = Wr[k]; }
        __syncthreads();
        int n0 = blockIdx.x * 16 + h * 8;
#pragma unroll
        for (int t = 0; t < 8; t++) {
            int n = n0 + t;
            if (n >= NN) break;
            float al = 0.f, ar = 0.f;
#pragma unroll
            for (int k = 0; k < 10; k++) {
                float xv = x[n * 10 + k];
                al = fmaf(xv, swl[k * 128 + c], al);
                ar = fmaf(xv, swr[k * 128 + c], ar);
            }
            g_xl1[n * 128 + c] = al;
            g_xr1[n * 128 + c] = ar;
        }
    } else {
        int e = (blockIdx.x - PRE_BLOCKS) * 256 + threadIdx.x;
        if (e < NE) {
            unsigned dst = (unsigned)ei[NE + e];
            if (dst < NN) atomicAdd(&g_cnt[dst], 1);
        }
    }
}

// ---------------- launch 2: full scan, last-block finalize ----------------
__global__ __launch_bounds__(1024) void k_scanAll() {
    __shared__ int sh[1024];
    __shared__ int sbs[64];
    __shared__ int isLast;
    int tid = threadIdx.x;
    int i = blockIdx.x * 1024 + tid;
    int v = (i < NN) ? g_cnt[i] : 0;
    sh[tid] = v;
    __syncthreads();
    for (int off = 1; off < 1024; off <<= 1) {
        int t = (tid >= off) ? sh[tid - off] : 0;
        __syncthreads();
        sh[tid] += t;
        __syncthreads();
    }
    int incl = sh[tid];
    if (i < NN) g_rowptr[i] = incl - v;
    if (tid == 1023) g_blocksum[blockIdx.x] = incl;
    __threadfence();
    if (tid == 0) isLast = (atomicAdd(&g_scan_done, 1) == (int)gridDim.x - 1);
    __syncthreads();
    if (!isLast) return;
    __threadfence();

    if (tid < 64) sbs[tid] = (tid < (int)gridDim.x) ? g_blocksum[tid] : 0;
    __syncthreads();
    if (tid == 0) {
        int run = 0;
        for (int b = 0; b < 64; b++) { int t = sbs[b]; sbs[b] = run; run += t; }
    }
    __syncthreads();
    for (int j = tid; j < NN; j += 1024) {
        int r = g_rowptr[j] + sbs[j >> 10];
        g_rowptr[j] = r;
        g_cnt[j] = r;
    }
    if (tid == 0) { g_rowptr[NN] = NE; g_scan_done = 0; }
}

// ---------------- launch 3: scatter ----------------
__global__ void k_scatter(const int* __restrict__ ei,
                          const float* __restrict__ edge_attr) {
    int e = blockIdx.x * blockDim.x + threadIdx.x;
    if (e < NE) {
        unsigned dst = (unsigned)ei[NE + e];
        unsigned src = (unsigned)ei[e];
        if (dst < NN && src < NN) {
            int pos = atomicAdd(&g_cnt[dst], 1);
            g_src[pos] = (int)src;
            g_ea[pos]  = edge_attr[e];
        }
    }
}

// ---------------- launch 4 (NCU SLOT): layer-1 agg — 2 edge-groups x 16 lanes ----------
// lane: group g = lane>>4 (its own edge stream), k = lane&15, channels cb = 8k..8k+8
// (all within head k>>2). Logit reduce = 2 shfls over the 4-lane head cluster.
__global__ __launch_bounds__(256) void k_agg1(const float* __restrict__ att1,
                                              const float* __restrict__ W1e,
                                              const float* __restrict__ b1,
                                              const float* __restrict__ g1,
                                              const float* __restrict__ be1) {
    int warp = threadIdx.x >> 5, lane = threadIdx.x & 31;
    int node = blockIdx.x * 8 + warp;
    if (node >= NN) return;
    int g = lane >> 4;
    int cb = (lane & 15) * 8;

    const float L2E = 1.4426950408889634f;
    float4 weA = *(const float4*)(W1e + cb);
    float4 weB = *(const float4*)(W1e + cb + 4);
    float4 atA = *(const float4*)(att1 + cb);
    float4 atB = *(const float4*)(att1 + cb + 4);
    atA.x *= L2E; atA.y *= L2E; atA.z *= L2E; atA.w *= L2E;
    atB.x *= L2E; atB.y *= L2E; atB.z *= L2E; atB.w *= L2E;
    float4 xlA = *(const float4*)(g_xl1 + node * 128 + cb);
    float4 xlB = *(const float4*)(g_xl1 + node * 128 + cb + 4);
    float4 acA = make_float4(0.f, 0.f, 0.f, 0.f);
    float4 acB = make_float4(0.f, 0.f, 0.f, 0.f);
    float den = 0.f;

    int p0 = g_rowptr[node], p1 = g_rowptr[node + 1];
    int iters = (p1 - p0 + 1) >> 1;
    int p = p0 + g;
    for (int it = 0; it < iters; it++, p += 2) {
        bool valid = (p < p1);
        int pc = valid ? p : p0;
        int s = g_src[pc];
        float eav = g_ea[pc];
        const float* xrp = g_xr1 + s * 128 + cb;
        float4 xrA = *(const float4*)xrp;
        float4 xrB = *(const float4*)(xrp + 4);
        float t, lg;
        t = fmaf(eav, weA.x, xlA.x + xrA.x); t = fmaxf(t, 0.2f * t); lg = t * atA.x;
        t = fmaf(eav, weA.y, xlA.y + xrA.y); t = fmaxf(t, 0.2f * t); lg = fmaf(t, atA.y, lg);
        t = fmaf(eav, weA.z, xlA.z + xrA.z); t = fmaxf(t, 0.2f * t); lg = fmaf(t, atA.z, lg);
        t = fmaf(eav, weA.w, xlA.w + xrA.w); t = fmaxf(t, 0.2f * t); lg = fmaf(t, atA.w, lg);
        t = fmaf(eav, weB.x, xlB.x + xrB.x); t = fmaxf(t, 0.2f * t); lg = fmaf(t, atB.x, lg);
        t = fmaf(eav, weB.y, xlB.y + xrB.y); t = fmaxf(t, 0.2f * t); lg = fmaf(t, atB.y, lg);
        t = fmaf(eav, weB.z, xlB.z + xrB.z); t = fmaxf(t, 0.2f * t); lg = fmaf(t, atB.z, lg);
        t = fmaf(eav, weB.w, xlB.w + xrB.w); t = fmaxf(t, 0.2f * t); lg = fmaf(t, atB.w, lg);
        lg += __shfl_xor_sync(0xffffffffu, lg, 1);
        lg += __shfl_xor_sync(0xffffffffu, lg, 2);
        lg = valid ? lg : -1e30f;
        float w = ex2(lg);              // att pre-scaled by log2e
        den += w;
        acA.x = fmaf(w, xrA.x, acA.x); acA.y = fmaf(w, xrA.y, acA.y);
        acA.z = fmaf(w, xrA.z, acA.z); acA.w = fmaf(w, xrA.w, acA.w);
        acB.x = fmaf(w, xrB.x, acB.x); acB.y = fmaf(w, xrB.y, acB.y);
        acB.z = fmaf(w, xrB.z, acB.z); acB.w = fmaf(w, xrB.w, acB.w);
    }
    // merge the two edge-groups
    acA.x += __shfl_xor_sync(0xffffffffu, acA.x, 16);
    acA.y += __shfl_xor_sync(0xffffffffu, acA.y, 16);
    acA.z += __shfl_xor_sync(0xffffffffu, acA.z, 16);
    acA.w += __shfl_xor_sync(0xffffffffu, acA.w, 16);
    acB.x += __shfl_xor_sync(0xffffffffu, acB.x, 16);
    acB.y += __shfl_xor_sync(0xffffffffu, acB.y, 16);
    acB.z += __shfl_xor_sync(0xffffffffu, acB.z, 16);
    acB.w += __shfl_xor_sync(0xffffffffu, acB.w, 16);
    den   += __shfl_xor_sync(0xffffffffu, den, 16);

    float inv = (den > 0.f) ? (1.f / den) : 0.f;
    float4 bbA = *(const float4*)(b1 + cb);
    float4 bbB = *(const float4*)(b1 + cb + 4);
    float o0 = acA.x * inv + bbA.x, o1 = acA.y * inv + bbA.y;
    float o2 = acA.z * inv + bbA.z, o3 = acA.w * inv + bbA.w;
    float o4 = acB.x * inv + bbB.x, o5 = acB.y * inv + bbB.y;
    float o6 = acB.z * inv + bbB.z, o7 = acB.w * inv + bbB.w;

    // LayerNorm over 128 (each channel present in both groups -> divide by 256)
    float s = o0 + o1 + o2 + o3 + o4 + o5 + o6 + o7;
#pragma unroll
    for (int off = 16; off; off >>= 1) s += __shfl_xor_sync(0xffffffffu, s, off);
    float mu = s * (1.f / 256.f);
    float d0 = o0 - mu, d1 = o1 - mu, d2 = o2 - mu, d3 = o3 - mu;
    float d4 = o4 - mu, d5 = o5 - mu, d6 = o6 - mu, d7 = o7 - mu;
    float vs = fmaf(d0, d0, fmaf(d1, d1, fmaf(d2, d2, d3 * d3)))
             + fmaf(d4, d4, fmaf(d5, d5, fmaf(d6, d6, d7 * d7)));
#pragma unroll
    for (int off = 16; off; off >>= 1) vs += __shfl_xor_sync(0xffffffffu, vs, off);
    float rstd = rsqrtf(vs * (1.f / 256.f) + 1e-5f);

    if (g == 0) {
        float4 ggA = *(const float4*)(g1  + cb);
        float4 ggB = *(const float4*)(g1  + cb + 4);
        float4 beA = *(const float4*)(be1 + cb);
        float4 beB = *(const float4*)(be1 + cb + 4);
        float y0 = d0 * rstd * ggA.x + beA.x; y0 = (y0 > 0.f) ? y0 : expm1f(y0);
        float y1 = d1 * rstd * ggA.y + beA.y; y1 = (y1 > 0.f) ? y1 : expm1f(y1);
        float y2 = d2 * rstd * ggA.z + beA.z; y2 = (y2 > 0.f) ? y2 : expm1f(y2);
        float y3 = d3 * rstd * ggA.w + beA.w; y3 = (y3 > 0.f) ? y3 : expm1f(y3);
        float y4 = d4 * rstd * ggB.x + beB.x; y4 = (y4 > 0.f) ? y4 : expm1f(y4);
        float y5 = d5 * rstd * ggB.y + beB.y; y5 = (y5 > 0.f) ? y5 : expm1f(y5);
        float y6 = d6 * rstd * ggB.z + beB.z; y6 = (y6 > 0.f) ? y6 : expm1f(y6);
        float y7 = d7 * rstd * ggB.w + beB.w; y7 = (y7 > 0.f) ? y7 : expm1f(y7);
        *(float4*)(g_h1 + node * 128 + cb)     = make_float4(y0, y1, y2, y3);
        *(float4*)(g_h1 + node * 128 + cb + 4) = make_float4(y4, y5, y6, y7);
    }
}

// ---------------- launch 5: layer-2 dual projection via tf32 mma.sync (R13 exact) ----
__device__ __forceinline__ unsigned f2tf(float x) {
    unsigned r;
    asm("cvt.rna.tf32.f32 %0, %1;" : "=r"(r) : "f"(x));
    return r;
}

#define MMA_TF32(C, A0, A1, A2, A3, B0, B1)                                   \
    asm volatile("mma.sync.aligned.m16n8k8.row.col.f32.tf32.tf32.f32 "        \
                 "{%0,%1,%2,%3}, {%4,%5,%6,%7}, {%8,%9}, {%0,%1,%2,%3};"      \
                 : "+f"((C)[0]), "+f"((C)[1]), "+f"((C)[2]), "+f"((C)[3])     \
                 : "r"(A0), "r"(A1), "r"(A2), "r"(A3), "r"(B0), "r"(B1))

__global__ __launch_bounds__(256) void k_proj2(const float* __restrict__ Wl,
                                               const float* __restrict__ Wr) {
    int warp = threadIdx.x >> 5, lane = threadIdx.x & 31;
    int gid = lane >> 2, tig = lane & 3;
    const float* W    = (warp >> 2) ? Wr : Wl;
    float*       outp = (warp >> 2) ? g_xr2 : g_xl2;
    int nbase = blockIdx.x * 64 + (warp & 3) * 16;
    int row0 = nbase + gid;
    int row1 = nbase + gid + 8;
    const float* h0 = g_h1 + (unsigned)min(row0, NN - 1) * 128;
    const float* h1p = g_h1 + (unsigned)min(row1, NN - 1) * 128;

    float c[8][4];
#pragma unroll
    for (int nt = 0; nt < 8; nt++)
        c[nt][0] = c[nt][1] = c[nt][2] = c[nt][3] = 0.f;

#pragma unroll
    for (int kt = 0; kt < 16; kt++) {
        int k0 = kt * 8 + tig, k1 = k0 + 4;
        float fa0 = h0[k0], fa1 = h1p[k0], fa2 = h0[k1], fa3 = h1p[k1];
        unsigned a0 = f2tf(fa0), a1 = f2tf(fa1), a2 = f2tf(fa2), a3 = f2tf(fa3);
        unsigned al0 = f2tf(fa0 - __uint_as_float(a0));
        unsigned al1 = f2tf(fa1 - __uint_as_float(a1));
        unsigned al2 = f2tf(fa2 - __uint_as_float(a2));
        unsigned al3 = f2tf(fa3 - __uint_as_float(a3));
#pragma unroll
        for (int nt = 0; nt < 8; nt++) {
            int n = nt * 8 + gid;
            float fb0 = W[k0 * 64 + n], fb1 = W[k1 * 64 + n];
            unsigned b0 = f2tf(fb0), b1 = f2tf(fb1);
            unsigned bl0 = f2tf(fb0 - __uint_as_float(b0));
            unsigned bl1 = f2tf(fb1 - __uint_as_float(b1));
            MMA_TF32(c[nt], al0, al1, al2, al3, b0, b1);    // lo * hi
            MMA_TF32(c[nt], a0, a1, a2, a3, bl0, bl1);      // hi * lo
            MMA_TF32(c[nt], a0, a1, a2, a3, b0, b1);        // hi * hi
        }
    }

#pragma unroll
    for (int nt = 0; nt < 8; nt++) {
        int col = nt * 8 + tig * 2;
        if (row0 < NN) *(float2*)&outp[row0 * 64 + col] = make_float2(c[nt][0], c[nt][1]);
        if (row1 < NN) *(float2*)&outp[row1 * 64 + col] = make_float2(c[nt][2], c[nt][3]);
    }
}

// ---------------- launch 6: layer-2 agg — 4 edge-groups x 8 lanes + g_cnt re-zero ----
// lane: group g = lane>>3, k = lane&7, channels cb = 8k..8k+8 (of 64).
__global__ __launch_bounds__(256) void k_agg2(const float* __restrict__ att2,
                                              const float* __restrict__ W2e,
                                              const float* __restrict__ b2,
                                              const float* __restrict__ g2,
                                              const float* __restrict__ be2,
                                              float* __restrict__ out) {
    int warp = threadIdx.x >> 5, lane = threadIdx.x & 31;
    int node0 = blockIdx.x * 8;
    if (threadIdx.x < 8 && node0 + threadIdx.x < NN) g_cnt[node0 + threadIdx.x] = 0;

    int node = node0 + warp;
    if (node >= NN) return;
    int g = lane >> 3;
    int cb = (lane & 7) * 8;

    const float L2E = 1.4426950408889634f;
    float4 weA = *(const float4*)(W2e + cb);
    float4 weB = *(const float4*)(W2e + cb + 4);
    float4 atA = *(const float4*)(att2 + cb);
    float4 atB = *(const float4*)(att2 + cb + 4);
    atA.x *= L2E; atA.y *= L2E; atA.z *= L2E; atA.w *= L2E;
    atB.x *= L2E; atB.y *= L2E; atB.z *= L2E; atB.w *= L2E;
    float4 xlA = *(const float4*)(g_xl2 + node * 64 + cb);
    float4 xlB = *(const float4*)(g_xl2 + node * 64 + cb + 4);
    float4 acA = make_float4(0.f, 0.f, 0.f, 0.f);
    float4 acB = make_float4(0.f, 0.f, 0.f, 0.f);
    float den = 0.f;

    int p0 = g_rowptr[node], p1 = g_rowptr[node + 1];
    int iters = (p1 - p0 + 3) >> 2;
    int p = p0 + g;
    for (int it = 0; it < iters; it++, p += 4) {
        bool valid = (p < p1);
        int pc = valid ? p : p0;
        int s = g_src[pc];
        float eav = g_ea[pc];
        const float* xrp = g_xr2 + s * 64 + cb;
        float4 xrA = *(const float4*)xrp;
        float4 xrB = *(const float4*)(xrp + 4);
        float t, lg;
        t = fmaf(eav, weA.x, xlA.x + xrA.x); t = fmaxf(t, 0.2f * t); lg = t * atA.x;
        t = fmaf(eav, weA.y, xlA.y + xrA.y); t = fmaxf(t, 0.2f * t); lg = fmaf(t, atA.y, lg);
        t = fmaf(eav, weA.z, xlA.z + xrA.z); t = fmaxf(t, 0.2f * t); lg = fmaf(t, atA.z, lg);
        t = fmaf(eav, weA.w, xlA.w + xrA.w); t = fmaxf(t, 0.2f * t); lg = fmaf(t, atA.w, lg);
        t = fmaf(eav, weB.x, xlB.x + xrB.x); t = fmaxf(t, 0.2f * t); lg = fmaf(t, atB.x, lg);
        t = fmaf(eav, weB.y, xlB.y + xrB.y); t = fmaxf(t, 0.2f * t); lg = fmaf(t, atB.y, lg);
        t = fmaf(eav, weB.z, xlB.z + xrB.z); t = fmaxf(t, 0.2f * t); lg = fmaf(t, atB.z, lg);
        t = fmaf(eav, weB.w, xlB.w + xrB.w); t = fmaxf(t, 0.2f * t); lg = fmaf(t, atB.w, lg);
        lg += __shfl_xor_sync(0xffffffffu, lg, 1);
        lg += __shfl_xor_sync(0xffffffffu, lg, 2);
        lg += __shfl_xor_sync(0xffffffffu, lg, 4);
        lg = valid ? lg : -1e30f;
        float w = ex2(lg);
        den += w;
        acA.x = fmaf(w, xrA.x, acA.x); acA.y = fmaf(w, xrA.y, acA.y);
        acA.z = fmaf(w, xrA.z, acA.z); acA.w = fmaf(w, xrA.w, acA.w);
        acB.x = fmaf(w, xrB.x, acB.x); acB.y = fmaf(w, xrB.y, acB.y);
        acB.z = fmaf(w, xrB.z, acB.z); acB.w = fmaf(w, xrB.w, acB.w);
    }
    // merge the four edge-groups (xor 8, then xor 16)
#pragma unroll
    for (int off = 8; off <= 16; off <<= 1) {
        acA.x += __shfl_xor_sync(0xffffffffu, acA.x, off);
        acA.y += __shfl_xor_sync(0xffffffffu, acA.y, off);
        acA.z += __shfl_xor_sync(0xffffffffu, acA.z, off);
        acA.w += __shfl_xor_sync(0xffffffffu, acA.w, off);
        acB.x += __shfl_xor_sync(0xffffffffu, acB.x, off);
        acB.y += __shfl_xor_sync(0xffffffffu, acB.y, off);
        acB.z += __shfl_xor_sync(0xffffffffu, acB.z, off);
        acB.w += __shfl_xor_sync(0xffffffffu, acB.w, off);
        den   += __shfl_xor_sync(0xffffffffu, den, off);
    }

    float inv = (den > 0.f) ? (1.f / den) : 0.f;
    float4 bbA = *(const float4*)(b2 + cb);
    float4 bbB = *(const float4*)(b2 + cb + 4);
    float o0 = acA.x * inv + bbA.x, o1 = acA.y * inv + bbA.y;
    float o2 = acA.z * inv + bbA.z, o3 = acA.w * inv + bbA.w;
    float o4 = acB.x * inv + bbB.x, o5 = acB.y * inv + bbB.y;
    float o6 = acB.z * inv + bbB.z, o7 = acB.w * inv + bbB.w;

    // LayerNorm over 64 (each channel present in 4 groups -> divide by 256)
    float s = o0 + o1 + o2 + o3 + o4 + o5 + o6 + o7;
#pragma unroll
    for (int off = 16; off; off >>= 1) s += __shfl_xor_sync(0xffffffffu, s, off);
    float mu = s * (1.f / 256.f);
    float d0 = o0 - mu, d1 = o1 - mu, d2 = o2 - mu, d3 = o3 - mu;
    float d4 = o4 - mu, d5 = o5 - mu, d6 = o6 - mu, d7 = o7 - mu;
    float vs = fmaf(d0, d0, fmaf(d1, d1, fmaf(d2, d2, d3 * d3)))
             + fmaf(d4, d4, fmaf(d5, d5, fmaf(d6, d6, d7 * d7)));
#pragma unroll
    for (int off = 16; off; off >>= 1) vs += __shfl_xor_sync(0xffffffffu, vs, off);
    float rstd = rsqrtf(vs * (1.f / 256.f) + 1e-5f);

    if (g == 0) {
        float4 ggA = *(const float4*)(g2  + cb);
        float4 ggB = *(const float4*)(g2  + cb + 4);
        float4 beA = *(const float4*)(be2 + cb);
        float4 beB = *(const float4*)(be2 + cb + 4);
        float y0 = d0 * rstd * ggA.x + beA.x; y0 = (y0 > 0.f) ? y0 : expm1f(y0);
        float y1 = d1 * rstd * ggA.y + beA.y; y1 = (y1 > 0.f) ? y1 : expm1f(y1);
        float y2 = d2 * rstd * ggA.z + beA.z; y2 = (y2 > 0.f) ? y2 : expm1f(y2);
        float y3 = d3 * rstd * ggA.w + beA.w; y3 = (y3 > 0.f) ? y3 : expm1f(y3);
        float y4 = d4 * rstd * ggB.x + beB.x; y4 = (y4 > 0.f) ? y4 : expm1f(y4);
        float y5 = d5 * rstd * ggB.y + beB.y; y5 = (y5 > 0.f) ? y5 : expm1f(y5);
        float y6 = d6 * rstd * ggB.z + beB.z; y6 = (y6 > 0.f) ? y6 : expm1f(y6);
        float y7 = d7 * rstd * ggB.w + beB.w; y7 = (y7 > 0.f) ? y7 : expm1f(y7);
        *(float4*)(out + node * 64 + cb)     = make_float4(y0, y1, y2, y3);
        *(float4*)(out + node * 64 + cb + 4) = make_float4(y4, y5, y6, y7);
    }
}

// ---------------- launcher: 6 launches, agg1 in ncu's slot #4 ----------------
extern "C" void kernel_launch(void* const* d_in, const int* in_sizes, int n_in,
                              void* d_out, int out_size) {
    const float* x    = (const float*)d_in[0];
    const float* ea   = (const float*)d_in[1];
    const float* W1l  = (const float*)d_in[2];
    const float* W1r  = (const float*)d_in[3];
    const float* W1e  = (const float*)d_in[4];
    const float* att1 = (const float*)d_in[5];
    const float* b1   = (const float*)d_in[6];
    const float* ln1g = (const float*)d_in[7];
    const float* ln1b = (const float*)d_in[8];
    const float* W2l  = (const float*)d_in[9];
    const float* W2r  = (const float*)d_in[10];
    const float* W2e  = (const float*)d_in[11];
    const float* att2 = (const float*)d_in[12];
    const float* b2   = (const float*)d_in[13];
    const float* ln2g = (const float*)d_in[14];
    const float* ln2b = (const float*)d_in[15];
    const int*   ei   = (const int*)d_in[16];   // int32 [2, NE]
    float* out = (float*)d_out;

    const int NBLK_SCAN = (NN + 1023) / 1024;   // 49

    k_preHist<<<PRE_BLOCKS + HIST_BLOCKS, 256>>>(x, W1l, W1r, ei);
    k_scanAll<<<NBLK_SCAN, 1024>>>();
    k_scatter<<<(NE + 255) / 256, 256>>>(ei, ea);
    k_agg1   <<<(NN + 7) / 8, 256>>>(att1, W1e, b1, ln1g, ln1b);   // ncu slot #4
    k_proj2  <<<(NN + 63) / 64, 256>>>(W2l, W2r);
    k_agg2   <<<(NN + 7) / 8, 256>>>(att2, W2e, b2, ln2g, ln2b, out);
}

// round 17
// speedup vs baseline: 1.1068x; 1.1068x over previous
#include <cuda_runtime.h>
#include <cuda_bf16.h>
#include <math.h>

#define NN 50000
#define NE 800000

typedef unsigned long long u64;
#define ABS2MASK 0x7FFFFFFF7FFFFFFFull

__device__ __forceinline__ u64 pack2(float lo, float hi) {
    u64 r;
    asm("mov.b64 %0, {%1,%2};" : "=l"(r) : "r"(__float_as_uint(lo)), "r"(__float_as_uint(hi)));
    return r;
}
__device__ __forceinline__ void unpack2(u64 v, float& lo, float& hi) {
    unsigned a, b;
    asm("mov.b64 {%0,%1}, %2;" : "=r"(a), "=r"(b) : "l"(v));
    lo = __uint_as_float(a); hi = __uint_as_float(b);
}
__device__ __forceinline__ u64 add2(u64 a, u64 b) {
    u64 r; asm("add.rn.f32x2 %0, %1, %2;" : "=l"(r) : "l"(a), "l"(b)); return r;
}
__device__ __forceinline__ u64 fma2(u64 a, u64 b, u64 c) {
    u64 r; asm("fma.rn.f32x2 %0, %1, %2, %3;" : "=l"(r) : "l"(a), "l"(b), "l"(c)); return r;
}
__device__ __forceinline__ float ex2f(float x) {
    float r; asm("ex2.approx.f32 %0, %1;" : "=f"(r) : "f"(x)); return r;
}

// ---------------- device scratch ----------------
__device__ float g_xl1[NN * 128];
__device__ float g_xr1[NN * 128];
__device__ float g_h1 [NN * 128];
__device__ float g_xl2[NN * 64];
__device__ float g_xr2[NN * 64];
__device__ int   g_cnt[NN];
__device__ int   g_rowptr[NN + 1];
__device__ int   g_blocksum[64];
__device__ int   g_src[NE];
__device__ float g_ea [NE];

// ---------------- launch 1: zero counters + layer-1 projections ----------------
__global__ __launch_bounds__(128) void k_pre(const float* __restrict__ x,
                                             const float* __restrict__ Wl,
                                             const float* __restrict__ Wr) {
    __shared__ float swl[10 * 128];
    __shared__ float swr[10 * 128];
    int c = threadIdx.x;
    int n0 = blockIdx.x * 8;
    if (c < 8 && n0 + c < NN) g_cnt[n0 + c] = 0;
    for (int k = c; k < 10 * 128; k += 128) { swl[k] = Wl[k]; swr[k] = Wr[k]; }
    __syncthreads();
#pragma unroll
    for (int t = 0; t < 8; t++) {
        int n = n0 + t;
        if (n >= NN) break;
        float al = 0.f, ar = 0.f;
#pragma unroll
        for (int k = 0; k < 10; k++) {
            float xv = x[n * 10 + k];
            al = fmaf(xv, swl[k * 128 + c], al);
            ar = fmaf(xv, swr[k * 128 + c], ar);
        }
        g_xl1[n * 128 + c] = al;
        g_xr1[n * 128 + c] = ar;
    }
}

// ---------------- launch 2: histogram ----------------
__global__ void k_hist(const int* __restrict__ ei) {
    int e = blockIdx.x * blockDim.x + threadIdx.x;
    if (e < NE) {
        unsigned dst = (unsigned)ei[NE + e];
        if (dst < NN) atomicAdd(&g_cnt[dst], 1);
    }
}

// ---------------- launch 3: per-block scan ----------------
__global__ void k_scan1() {
    __shared__ int sh[1024];
    int i = blockIdx.x * 1024 + threadIdx.x;
    int v = (i < NN) ? g_cnt[i] : 0;
    sh[threadIdx.x] = v;
    __syncthreads();
    for (int off = 1; off < 1024; off <<= 1) {
        int t = (threadIdx.x >= off) ? sh[threadIdx.x - off] : 0;
        __syncthreads();
        sh[threadIdx.x] += t;
        __syncthreads();
    }
    int incl = sh[threadIdx.x];
    if (i < NN) g_rowptr[i] = incl - v;
    if (threadIdx.x == 1023) g_blocksum[blockIdx.x] = incl;
}

// ---------------- launch 4: finalize scan ----------------
__global__ __launch_bounds__(256) void k_scan3(int nblk) {
    __shared__ int sbs[64];
    int tid = threadIdx.x;
    if (tid < 64) sbs[tid] = (tid < nblk) ? g_blocksum[tid] : 0;
    __syncthreads();
    if (tid == 0) {
        int run = 0;
#pragma unroll
        for (int b = 0; b < 64; b++) { int t = sbs[b]; sbs[b] = run; run += t; }
    }
    __syncthreads();
    int i = blockIdx.x * 256 + tid;
    if (i < NN) {
        int r = g_rowptr[i] + sbs[i >> 10];
        g_rowptr[i] = r;
        g_cnt[i] = r;
    }
    if (i == 0) g_rowptr[NN] = NE;
}

// ---------------- launch 5: scatter ----------------
__global__ void k_scatter(const int* __restrict__ ei,
                          const float* __restrict__ edge_attr) {
    int e = blockIdx.x * blockDim.x + threadIdx.x;
    if (e < NE) {
        unsigned dst = (unsigned)ei[NE + e];
        unsigned src = (unsigned)ei[e];
        if (dst < NN && src < NN) {
            int pos = atomicAdd(&g_cnt[dst], 1);
            g_src[pos] = (int)src;
            g_ea[pos]  = edge_attr[e];
        }
    }
}

// ---------------- launch 6: layer-1 agg (R13 mapping, f32x2-packed math) ----------------
// lane owns 4 consecutive channels of its head (head = lane>>3); logit reduce = 3 shfls.
// leaky fold: att*leaky(t) = (0.6 att)t + (0.4 att)|t|;  ex2 with att pre-scaled by log2e.
__global__ __launch_bounds__(256) void k_agg1(const float* __restrict__ att1,
                                              const float* __restrict__ W1e,
                                              const float* __restrict__ b1,
                                              const float* __restrict__ g1,
                                              const float* __restrict__ be1) {
    int warp = threadIdx.x >> 5, lane = threadIdx.x & 31;
    int node = blockIdx.x * 8 + warp;
    if (node >= NN) return;

    int cb = (lane >> 3) * 32 + (lane & 7) * 4;
    const float L2E = 1.4426950408889634f;

    float4 att = *(const float4*)(att1 + cb);
    float4 we  = *(const float4*)(W1e  + cb);
    float4 xli = *(const float4*)(g_xl1 + node * 128 + cb);
    u64 we01 = pack2(we.x, we.y),  we23 = pack2(we.z, we.w);
    u64 xl01 = pack2(xli.x, xli.y), xl23 = pack2(xli.z, xli.w);
    u64 a1_01 = pack2(0.6f * L2E * att.x, 0.6f * L2E * att.y);
    u64 a1_23 = pack2(0.6f * L2E * att.z, 0.6f * L2E * att.w);
    u64 a2_01 = pack2(0.4f * L2E * att.x, 0.4f * L2E * att.y);
    u64 a2_23 = pack2(0.4f * L2E * att.z, 0.4f * L2E * att.w);
    u64 ac01 = 0ull, ac23 = 0ull;
    float den = 0.f;

    const ulonglong2* xr_base = (const ulonglong2*)g_xr1;   // [node][32 x 16B]
    int fidx = cb >> 2;

    int p0 = g_rowptr[node], p1 = g_rowptr[node + 1];
    int p = p0;
    for (; p + 1 < p1; p += 2) {
        int   s0  = g_src[p],  s1  = g_src[p + 1];
        float ea0 = g_ea[p],   ea1 = g_ea[p + 1];
        ulonglong2 xr0 = xr_base[s0 * 32 + fidx];
        ulonglong2 xr1 = xr_base[s1 * 32 + fidx];

        u64 e2 = pack2(ea0, ea0);
        u64 t01 = fma2(e2, we01, add2(xl01, xr0.x));
        u64 t23 = fma2(e2, we23, add2(xl23, xr0.y));
        u64 lgp = fma2(a1_01, t01, fma2(a2_01, t01 & ABS2MASK,
                  fma2(a1_23, t23, fma2(a2_23, t23 & ABS2MASK, 0ull))));
        float llo, lhi; unpack2(lgp, llo, lhi);
        float lg0 = llo + lhi;

        e2 = pack2(ea1, ea1);
        t01 = fma2(e2, we01, add2(xl01, xr1.x));
        t23 = fma2(e2, we23, add2(xl23, xr1.y));
        lgp = fma2(a1_01, t01, fma2(a2_01, t01 & ABS2MASK,
              fma2(a1_23, t23, fma2(a2_23, t23 & ABS2MASK, 0ull))));
        unpack2(lgp, llo, lhi);
        float lg1 = llo + lhi;

#pragma unroll
        for (int off = 4; off; off >>= 1) {
            lg0 += __shfl_xor_sync(0xffffffffu, lg0, off);
            lg1 += __shfl_xor_sync(0xffffffffu, lg1, off);
        }
        float w0 = ex2f(lg0);
        float w1 = ex2f(lg1);
        den += w0 + w1;
        u64 w02 = pack2(w0, w0), w12 = pack2(w1, w1);
        ac01 = fma2(w02, xr0.x, fma2(w12, xr1.x, ac01));
        ac23 = fma2(w02, xr0.y, fma2(w12, xr1.y, ac23));
    }
    if (p < p1) {
        int   s0  = g_src[p];
        float ea0 = g_ea[p];
        ulonglong2 xr0 = xr_base[s0 * 32 + fidx];
        u64 e2 = pack2(ea0, ea0);
        u64 t01 = fma2(e2, we01, add2(xl01, xr0.x));
        u64 t23 = fma2(e2, we23, add2(xl23, xr0.y));
        u64 lgp = fma2(a1_01, t01, fma2(a2_01, t01 & ABS2MASK,
                  fma2(a1_23, t23, fma2(a2_23, t23 & ABS2MASK, 0ull))));
        float llo, lhi; unpack2(lgp, llo, lhi);
        float lg0 = llo + lhi;
#pragma unroll
        for (int off = 4; off; off >>= 1)
            lg0 += __shfl_xor_sync(0xffffffffu, lg0, off);
        float w0 = ex2f(lg0);
        den += w0;
        u64 w02 = pack2(w0, w0);
        ac01 = fma2(w02, xr0.x, ac01);
        ac23 = fma2(w02, xr0.y, ac23);
    }

    float a0, a1, a2, a3;
    unpack2(ac01, a0, a1);
    unpack2(ac23, a2, a3);
    float inv = (den > 0.f) ? (1.f / den) : 0.f;
    float4 bb = *(const float4*)(b1 + cb);
    float o0 = a0 * inv + bb.x;
    float o1 = a1 * inv + bb.y;
    float o2 = a2 * inv + bb.z;
    float o3 = a3 * inv + bb.w;

    float s = o0 + o1 + o2 + o3;
#pragma unroll
    for (int off = 16; off; off >>= 1) s += __shfl_xor_sync(0xffffffffu, s, off);
    float mu = s * (1.f / 128.f);
    float d0 = o0 - mu, d1 = o1 - mu, d2 = o2 - mu, d3 = o3 - mu;
    float vs = fmaf(d0, d0, fmaf(d1, d1, fmaf(d2, d2, d3 * d3)));
#pragma unroll
    for (int off = 16; off; off >>= 1) vs += __shfl_xor_sync(0xffffffffu, vs, off);
    float rstd = rsqrtf(vs * (1.f / 128.f) + 1e-5f);

    float4 gg = *(const float4*)(g1  + cb);
    float4 be = *(const float4*)(be1 + cb);
    float y0 = d0 * rstd * gg.x + be.x; y0 = (y0 > 0.f) ? y0 : expm1f(y0);
    float y1 = d1 * rstd * gg.y + be.y; y1 = (y1 > 0.f) ? y1 : expm1f(y1);
    float y2 = d2 * rstd * gg.z + be.z; y2 = (y2 > 0.f) ? y2 : expm1f(y2);
    float y3 = d3 * rstd * gg.w + be.w; y3 = (y3 > 0.f) ? y3 : expm1f(y3);
    *(float4*)(g_h1 + node * 128 + cb) = make_float4(y0, y1, y2, y3);
}

// ---------------- launch 7: layer-2 dual projection via tf32 mma.sync (R13 exact) ----
__device__ __forceinline__ unsigned f2tf(float x) {
    unsigned r;
    asm("cvt.rna.tf32.f32 %0, %1;" : "=r"(r) : "f"(x));
    return r;
}

#define MMA_TF32(C, A0, A1, A2, A3, B0, B1)                                   \
    asm volatile("mma.sync.aligned.m16n8k8.row.col.f32.tf32.tf32.f32 "        \
                 "{%0,%1,%2,%3}, {%4,%5,%6,%7}, {%8,%9}, {%0,%1,%2,%3};"      \
                 : "+f"((C)[0]), "+f"((C)[1]), "+f"((C)[2]), "+f"((C)[3])     \
                 : "r"(A0), "r"(A1), "r"(A2), "r"(A3), "r"(B0), "r"(B1))

__global__ __launch_bounds__(256) void k_proj2(const float* __restrict__ Wl,
                                               const float* __restrict__ Wr) {
    int warp = threadIdx.x >> 5, lane = threadIdx.x & 31;
    int gid = lane >> 2, tig = lane & 3;
    const float* W    = (warp >> 2) ? Wr : Wl;
    float*       outp = (warp >> 2) ? g_xr2 : g_xl2;
    int nbase = blockIdx.x * 64 + (warp & 3) * 16;
    int row0 = nbase + gid;
    int row1 = nbase + gid + 8;
    const float* h0 = g_h1 + (unsigned)min(row0, NN - 1) * 128;
    const float* h1p = g_h1 + (unsigned)min(row1, NN - 1) * 128;

    float c[8][4];
#pragma unroll
    for (int nt = 0; nt < 8; nt++)
        c[nt][0] = c[nt][1] = c[nt][2] = c[nt][3] = 0.f;

#pragma unroll
    for (int kt = 0; kt < 16; kt++) {
        int k0 = kt * 8 + tig, k1 = k0 + 4;
        float fa0 = h0[k0], fa1 = h1p[k0], fa2 = h0[k1], fa3 = h1p[k1];
        unsigned a0 = f2tf(fa0), a1 = f2tf(fa1), a2 = f2tf(fa2), a3 = f2tf(fa3);
        unsigned al0 = f2tf(fa0 - __uint_as_float(a0));
        unsigned al1 = f2tf(fa1 - __uint_as_float(a1));
        unsigned al2 = f2tf(fa2 - __uint_as_float(a2));
        unsigned al3 = f2tf(fa3 - __uint_as_float(a3));
#pragma unroll
        for (int nt = 0; nt < 8; nt++) {
            int n = nt * 8 + gid;
            float fb0 = W[k0 * 64 + n], fb1 = W[k1 * 64 + n];
            unsigned b0 = f2tf(fb0), b1 = f2tf(fb1);
            unsigned bl0 = f2tf(fb0 - __uint_as_float(b0));
            unsigned bl1 = f2tf(fb1 - __uint_as_float(b1));
            MMA_TF32(c[nt], al0, al1, al2, al3, b0, b1);    // lo * hi
            MMA_TF32(c[nt], a0, a1, a2, a3, bl0, bl1);      // hi * lo
            MMA_TF32(c[nt], a0, a1, a2, a3, b0, b1);        // hi * hi
        }
    }

#pragma unroll
    for (int nt = 0; nt < 8; nt++) {
        int col = nt * 8 + tig * 2;
        if (row0 < NN) *(float2*)&outp[row0 * 64 + col] = make_float2(c[nt][0], c[nt][1]);
        if (row1 < NN) *(float2*)&outp[row1 * 64 + col] = make_float2(c[nt][2], c[nt][3]);
    }
}

// ---------------- launch 8: layer-2 agg (R13 mapping, f32x2-packed math) ----------------
__global__ __launch_bounds__(256) void k_agg2(const float* __restrict__ att2,
                                              const float* __restrict__ W2e,
                                              const float* __restrict__ b2,
                                              const float* __restrict__ g2,
                                              const float* __restrict__ be2,
                                              float* __restrict__ out) {
    int warp = threadIdx.x >> 5, lane = threadIdx.x & 31;
    int node = blockIdx.x * 8 + warp;
    if (node >= NN) return;

    int cb = lane * 2;
    const float L2E = 1.4426950408889634f;
    float2 att = *(const float2*)(att2 + cb);
    float2 wef = *(const float2*)(W2e  + cb);
    float2 xlf = *(const float2*)(g_xl2 + node * 64 + cb);
    u64 we2v = pack2(wef.x, wef.y);
    u64 xl2v = pack2(xlf.x, xlf.y);
    u64 a1v = pack2(0.6f * L2E * att.x, 0.6f * L2E * att.y);
    u64 a2v = pack2(0.4f * L2E * att.x, 0.4f * L2E * att.y);
    u64 acc = 0ull;
    float den = 0.f;
    const u64* xr_base = (const u64*)g_xr2;   // [node][32 x 8B]

    int p0 = g_rowptr[node], p1 = g_rowptr[node + 1];
    int p = p0;
    for (; p + 1 < p1; p += 2) {
        int   s0  = g_src[p],  s1  = g_src[p + 1];
        float ea0 = g_ea[p],   ea1 = g_ea[p + 1];
        u64 xr0 = xr_base[s0 * 32 + lane];
        u64 xr1 = xr_base[s1 * 32 + lane];

        u64 t0 = fma2(pack2(ea0, ea0), we2v, add2(xl2v, xr0));
        u64 t1 = fma2(pack2(ea1, ea1), we2v, add2(xl2v, xr1));
        u64 lp0 = fma2(a1v, t0, fma2(a2v, t0 & ABS2MASK, 0ull));
        u64 lp1 = fma2(a1v, t1, fma2(a2v, t1 & ABS2MASK, 0ull));
        float l0a, l0b, l1a, l1b;
        unpack2(lp0, l0a, l0b);
        unpack2(lp1, l1a, l1b);
        float lgA = l0a + l0b, lgB = l1a + l1b;
#pragma unroll
        for (int off = 16; off; off >>= 1) {
            lgA += __shfl_xor_sync(0xffffffffu, lgA, off);
            lgB += __shfl_xor_sync(0xffffffffu, lgB, off);
        }
        float w0 = ex2f(lgA);
        float w1 = ex2f(lgB);
        den += w0 + w1;
        acc = fma2(pack2(w0, w0), xr0, fma2(pack2(w1, w1), xr1, acc));
    }
    if (p < p1) {
        int   s0  = g_src[p];
        float ea0 = g_ea[p];
        u64 xr0 = xr_base[s0 * 32 + lane];
        u64 t0 = fma2(pack2(ea0, ea0), we2v, add2(xl2v, xr0));
        u64 lp0 = fma2(a1v, t0, fma2(a2v, t0 & ABS2MASK, 0ull));
        float l0a, l0b;
        unpack2(lp0, l0a, l0b);
        float lgA = l0a + l0b;
#pragma unroll
        for (int off = 16; off; off >>= 1)
            lgA += __shfl_xor_sync(0xffffffffu, lgA, off);
        float w0 = ex2f(lgA);
        den += w0;
        acc = fma2(pack2(w0, w0), xr0, acc);
    }

    float ac0, ac1;
    unpack2(acc, ac0, ac1);
    float inv = (den > 0.f) ? (1.f / den) : 0.f;
    float2 bb = *(const float2*)(b2 + cb);
    float o0 = ac0 * inv + bb.x;
    float o1 = ac1 * inv + bb.y;

    float s = o0 + o1;
#pragma unroll
    for (int off = 16; off; off >>= 1) s += __shfl_xor_sync(0xffffffffu, s, off);
    float mu = s * (1.f / 64.f);
    float d0 = o0 - mu, d1 = o1 - mu;
    float vs = fmaf(d0, d0, d1 * d1);
#pragma unroll
    for (int off = 16; off; off >>= 1) vs += __shfl_xor_sync(0xffffffffu, vs, off);
    float rstd = rsqrtf(vs * (1.f / 64.f) + 1e-5f);

    float2 gg = *(const float2*)(g2  + cb);
    float2 be = *(const float2*)(be2 + cb);
    float y0 = d0 * rstd * gg.x + be.x; y0 = (y0 > 0.f) ? y0 : expm1f(y0);
    float y1 = d1 * rstd * gg.y + be.y; y1 = (y1 > 0.f) ? y1 : expm1f(y1);
    *(float2*)(out + node * 64 + cb) = make_float2(y0, y1);
}

// ---------------- launcher: 8 launches (R13 structure) ----------------
extern "C" void kernel_launch(void* const* d_in, const int* in_sizes, int n_in,
                              void* d_out, int out_size) {
    const float* x    = (const float*)d_in[0];
    const float* ea   = (const float*)d_in[1];
    const float* W1l  = (const float*)d_in[2];
    const float* W1r  = (const float*)d_in[3];
    const float* W1e  = (const float*)d_in[4];
    const float* att1 = (const float*)d_in[5];
    const float* b1   = (const float*)d_in[6];
    const float* ln1g = (const float*)d_in[7];
    const float* ln1b = (const float*)d_in[8];
    const float* W2l  = (const float*)d_in[9];
    const float* W2r  = (const float*)d_in[10];
    const float* W2e  = (const float*)d_in[11];
    const float* att2 = (const float*)d_in[12];
    const float* b2   = (const float*)d_in[13];
    const float* ln2g = (const float*)d_in[14];
    const float* ln2b = (const float*)d_in[15];
    const int*   ei   = (const int*)d_in[16];   // int32 [2, NE]
    float* out = (float*)d_out;

    const int NBLK_SCAN = (NN + 1023) / 1024;   // 49

    k_pre    <<<(NN + 7) / 8, 128>>>(x, W1l, W1r);
    k_hist   <<<(NE + 255) / 256, 256>>>(ei);
    k_scan1  <<<NBLK_SCAN, 1024>>>();
    k_scan3  <<<(NN + 255) / 256, 256>>>(NBLK_SCAN);
    k_scatter<<<(NE + 255) / 256, 256>>>(ei, ea);
    k_agg1   <<<(NN + 7) / 8, 256>>>(att1, W1e, b1, ln1g, ln1b);
    k_proj2  <<<(NN + 63) / 64, 256>>>(W2l, W2r);
    k_agg2   <<<(NN + 7) / 8, 256>>>(att2, W2e, b2, ln2g, ln2b, out);
}